// round 5
// baseline (speedup 1.0000x reference)
#include <cuda_runtime.h>
#include <math.h>
#include <stdint.h>

#define THREADS 256

// strides (u32). ASTR==4 mod 32, BSTR==8 mod 32: conflict-free frag LDS.
#define ASTR 36
#define BSTR 72
#define HSTR 36

// smem layout (u32). A: 2 bufs x (hi 64x36 + lo 64x36). B: 2 bufs x (hi 32x72 + lo).
#define ABUF 4608
#define OFF_A 0
#define OFF_B 9216
#define OFF_H 18432
#define OFF_C2 23040
#define SMEM_U32 23104
#define SMEM_BYTES (SMEM_U32 * 4)   // 92416 B -> 2 CTAs/SM

__device__ float g_c2[8 * 64];
__device__ __align__(16) unsigned gW1hi[10 * 2048];   // [chunk][kpair][n]
__device__ __align__(16) unsigned gW1lo[10 * 2048];
__device__ __align__(16) unsigned gW2hi[2048];
__device__ __align__(16) unsigned gW2lo[2048];

// ---------------------------------------------------------------------------
// helpers
// ---------------------------------------------------------------------------
__device__ __forceinline__ unsigned s2u(const void* p) {
    unsigned a;
    asm("{ .reg .u64 t; cvta.to.shared.u64 t, %1; cvt.u32.u64 %0, t; }" : "=r"(a) : "l"(p));
    return a;
}

// pack pair (e = even k, o = odd k) -> bf16x2 hi + bf16x2 lo residual
__device__ __forceinline__ void bsplit(float e, float o, unsigned& ph, unsigned& pl) {
    asm("cvt.rn.bf16x2.f32 %0, %1, %2;" : "=r"(ph) : "f"(o), "f"(e));
    float eh = __uint_as_float(ph << 16);
    float oh = __uint_as_float(ph & 0xffff0000u);
    asm("cvt.rn.bf16x2.f32 %0, %1, %2;" : "=r"(pl) : "f"(o - oh), "f"(e - eh));
}

__device__ __forceinline__ void mma_bf16(float* c,
                                         unsigned a0, unsigned a1, unsigned a2, unsigned a3,
                                         unsigned b0, unsigned b1)
{
    asm volatile(
        "mma.sync.aligned.m16n8k16.row.col.f32.bf16.bf16.f32 "
        "{%0,%1,%2,%3}, {%4,%5,%6,%7}, {%8,%9}, {%0,%1,%2,%3};"
        : "+f"(c[0]), "+f"(c[1]), "+f"(c[2]), "+f"(c[3])
        : "r"(a0), "r"(a1), "r"(a2), "r"(a3), "r"(b0), "r"(b1));
}

__device__ __forceinline__ float gelu(float v) {
    return 0.5f * v * (1.0f + erff(v * 0.70710678118654752440f));
}

__device__ __forceinline__ void cpa16(unsigned dst, const void* src) {
    asm volatile("cp.async.ca.shared.global [%0], [%1], 16;" :: "r"(dst), "l"(src));
}
__device__ __forceinline__ void cpa_commit() {
    asm volatile("cp.async.commit_group;" ::: "memory");
}
__device__ __forceinline__ void cpa_wait0() {
    asm volatile("cp.async.wait_group 0;" ::: "memory");
}

// ---------------------------------------------------------------------------
// prep: split W1/W2 into bf16x2 hi/lo k-pair tiles [chunk][kpair][n]
// ---------------------------------------------------------------------------
__global__ void prep_kernel(const float* __restrict__ W1, const float* __restrict__ W2)
{
    int t = blockIdx.x * THREADS + threadIdx.x;
    if (t < 10 * 2048) {
        int c = t >> 11, kp = (t >> 6) & 31, n = t & 63;
        int k = c * 64 + 2 * kp;
        unsigned ph, pl;
        bsplit(W1[k * 64 + n], W1[(k + 1) * 64 + n], ph, pl);
        gW1hi[t] = ph; gW1lo[t] = pl;
    }
    if (t < 2048) {
        int kp = t >> 6, n = t & 63;
        unsigned ph, pl;
        bsplit(W2[(2 * kp) * 64 + n], W2[(2 * kp + 1) * 64 + n], ph, pl);
        gW2hi[t] = ph; gW2lo[t] = pl;
    }
}

// ---------------------------------------------------------------------------
// ctx: attention collapses analytically (softmax pooling of a spatially
// constant value == the value). c2 = c + LN((c@Wv+bv)@Wo + bo + c).
// ---------------------------------------------------------------------------
__global__ void ctx_kernel(const float* __restrict__ c,
                           const float* __restrict__ Wv, const float* __restrict__ bv,
                           const float* __restrict__ Wo, const float* __restrict__ bo,
                           const float* __restrict__ lng, const float* __restrict__ lnb,
                           float* __restrict__ outc2)
{
    __shared__ float sv[8][64];
    __shared__ float st[8][64];
    int b = threadIdx.x >> 5;
    int lane = threadIdx.x & 31;

    #pragma unroll
    for (int oo = 0; oo < 2; oo++) {
        int o = lane + 32 * oo;
        float acc = bv[o];
        #pragma unroll 8
        for (int i = 0; i < 64; i++) acc += c[b * 64 + i] * Wv[i * 64 + o];
        sv[b][o] = acc;
    }
    __syncwarp();
    #pragma unroll
    for (int oo = 0; oo < 2; oo++) {
        int o = lane + 32 * oo;
        float acc = bo[o] + c[b * 64 + o];
        #pragma unroll 8
        for (int i = 0; i < 64; i++) acc += sv[b][i] * Wo[i * 64 + o];
        st[b][o] = acc;
    }
    __syncwarp();
    float t0 = st[b][lane], t1 = st[b][lane + 32];
    float s = t0 + t1;
    #pragma unroll
    for (int off = 16; off; off >>= 1) s += __shfl_xor_sync(0xffffffffu, s, off);
    float m = s * (1.0f / 64.0f);
    float d0 = t0 - m, d1 = t1 - m;
    float q = d0 * d0 + d1 * d1;
    #pragma unroll
    for (int off = 16; off; off >>= 1) q += __shfl_xor_sync(0xffffffffu, q, off);
    float inv = rsqrtf(q * (1.0f / 64.0f) + 1e-5f);
    #pragma unroll
    for (int oo = 0; oo < 2; oo++) {
        int o = lane + 32 * oo;
        float a = (st[b][o] - m) * inv * lng[o] + lnb[o];
        float v2 = c[b * 64 + o] + a;
        g_c2[b * 64 + o] = v2;
        outc2[b * 64 + o] = v2;
    }
}

// ---------------------------------------------------------------------------
// main kernel: block = 64 px (half an image row). K-streamed GEMM1 with
// register accumulators, double-buffered A (perception chunks) and B
// (cp.async-prefetched W1 chunks). GEMM2 from smem H tile + W2.
// ---------------------------------------------------------------------------
__global__ __launch_bounds__(256, 2)
void nca_kernel(const float* __restrict__ x, const float* __restrict__ pk,
                const float* __restrict__ b1, const float* __restrict__ b2,
                float* __restrict__ y)
{
    extern __shared__ unsigned smem[];
    unsigned sbase = s2u(smem);
    float* sC2 = (float*)(smem + OFF_C2);

    int tid = threadIdx.x;
    int warp = tid >> 5, lane = tid & 31;
    int g = lane >> 2, tg = lane & 3;
    int mh = warp & 3, nh = warp >> 2;
    int m0 = mh << 4;         // 16-row m tile within 64 px
    int n0 = nh << 5;         // 32-col n half

    int bi = blockIdx.x;
    int w0 = (bi & 1) << 6;
    int h  = (bi >> 1) & 127;
    int b  = bi >> 8;

    int cp = tid & 31;        // k-pair within chunk
    int pg = tid >> 5;        // pixel subgroup: pixels pg + 8m
    const size_t imgbase = ((size_t)((b << 7) + h)) << 13;

    if (tid < 64) sC2[tid] = g_c2[b * 64 + tid];

    // prefetch B chunk 0
    {
        unsigned dbase = sbase + (OFF_B + 0 * ABUF) * 4;
        #pragma unroll
        for (int j = 0; j < 2; j++) {
            int q = tid + (j << 8);
            int kp = q >> 4, pos = q & 15;
            cpa16(dbase + (kp * BSTR + pos * 4) * 4, gW1hi + kp * 64 + pos * 4);
            cpa16(dbase + (2304 + kp * BSTR + pos * 4) * 4, gW1lo + kp * 64 + pos * 4);
        }
    }
    cpa_commit();
    __syncthreads();

    float aM[4][4] = {{0,0,0,0},{0,0,0,0},{0,0,0,0},{0,0,0,0}};
    float aC[4][4] = {{0,0,0,0},{0,0,0,0},{0,0,0,0},{0,0,0,0}};

    for (int i = 0; i < 10; i++) {
        int s = i & 1;
        unsigned* aHi = smem + OFF_A + s * ABUF;
        unsigned* aLo = aHi + 2304;

        // ---- produce A chunk i (64 px x 32 kpairs) ----
        if (i == 0) {
            #pragma unroll 4
            for (int m = 0; m < 8; m++) {
                int p = pg + (m << 3);
                float2 v = *(const float2*)(x + imgbase + ((size_t)(w0 + p) << 6) + (cp << 1));
                unsigned ph, pl; bsplit(v.x, v.y, ph, pl);
                aHi[p * ASTR + cp] = ph; aLo[p * ASTR + cp] = pl;
            }
        } else if (i == 1) {
            unsigned ph, pl; bsplit(sC2[cp << 1], sC2[(cp << 1) + 1], ph, pl);
            #pragma unroll
            for (int m = 0; m < 8; m++) {
                int p = pg + (m << 3);
                aHi[p * ASTR + cp] = ph; aLo[p * ASTR + cp] = pl;
            }
        } else {
            int di = (i - 2) >> 1;
            int hc = (i - 2) & 1;
            int d  = 1 << di;
            if (hc == 0) {
                // real depthwise dilated conv on x channels 2cp, 2cp+1
                int ch = cp << 1;
                const float* tp = pk + ((di << 7) + ch) * 9;
                float tap0[9], tap1[9];
                #pragma unroll
                for (int t9 = 0; t9 < 9; t9++) { tap0[t9] = tp[t9]; tap1[t9] = tp[9 + t9]; }
                const float* rp[3]; bool rv[3];
                #pragma unroll
                for (int t3 = 0; t3 < 3; t3++) {
                    int hh = h + (t3 - 1) * d;
                    rv[t3] = ((unsigned)hh < 128u);
                    rp[t3] = x + (((size_t)((b << 7) + (hh & 127))) << 13) + ch;
                }
                #pragma unroll 2
                for (int m = 0; m < 8; m++) {
                    int p = pg + (m << 3);
                    int w = w0 + p;
                    float a0 = 0.f, a1 = 0.f;
                    #pragma unroll
                    for (int t3 = 0; t3 < 3; t3++) {
                        if (rv[t3]) {
                            #pragma unroll
                            for (int dx = 0; dx < 3; dx++) {
                                int ww = w + (dx - 1) * d;
                                if ((unsigned)ww < 128u) {
                                    float2 v = *(const float2*)(rp[t3] + ((size_t)ww << 6));
                                    a0 += v.x * tap0[t3 * 3 + dx];
                                    a1 += v.y * tap1[t3 * 3 + dx];
                                }
                            }
                        }
                    }
                    unsigned ph, pl; bsplit(a0, a1, ph, pl);
                    aHi[p * ASTR + cp] = ph; aLo[p * ASTR + cp] = pl;
                }
            } else {
                // context half: conv of constant field = c2 * masked tap sums
                int ch = 64 + (cp << 1);
                const float* tp = pk + ((di << 7) + ch) * 9;
                float cs0[3] = {0, 0, 0}, cs1[3] = {0, 0, 0};
                #pragma unroll
                for (int t3 = 0; t3 < 3; t3++) {
                    int hh = h + (t3 - 1) * d;
                    if ((unsigned)hh < 128u) {
                        #pragma unroll
                        for (int dx = 0; dx < 3; dx++) {
                            cs0[dx] += tp[t3 * 3 + dx];
                            cs1[dx] += tp[9 + t3 * 3 + dx];
                        }
                    }
                }
                float c0 = sC2[ch - 64], c1 = sC2[ch - 63];
                #pragma unroll
                for (int m = 0; m < 8; m++) {
                    int p = pg + (m << 3);
                    int w = w0 + p;
                    float k0 = 0.f, k1 = 0.f;
                    #pragma unroll
                    for (int dx = 0; dx < 3; dx++) {
                        int ww = w + (dx - 1) * d;
                        if ((unsigned)ww < 128u) { k0 += cs0[dx]; k1 += cs1[dx]; }
                    }
                    unsigned ph, pl; bsplit(c0 * k0, c1 * k1, ph, pl);
                    aHi[p * ASTR + cp] = ph; aLo[p * ASTR + cp] = pl;
                }
            }
        }

        // B chunk i complete, all tiles visible after barrier
        cpa_wait0();
        __syncthreads();

        // prefetch next B chunk (W1 chunk i+1, or W2 when i==9) into buf s^1
        {
            const unsigned* srcHi = (i < 9) ? (gW1hi + (i + 1) * 2048) : gW2hi;
            const unsigned* srcLo = (i < 9) ? (gW1lo + (i + 1) * 2048) : gW2lo;
            unsigned dbase = sbase + (OFF_B + (s ^ 1) * ABUF) * 4;
            #pragma unroll
            for (int j = 0; j < 2; j++) {
                int q = tid + (j << 8);
                int kp = q >> 4, pos = q & 15;
                cpa16(dbase + (kp * BSTR + pos * 4) * 4, srcHi + kp * 64 + pos * 4);
                cpa16(dbase + (2304 + kp * BSTR + pos * 4) * 4, srcLo + kp * 64 + pos * 4);
            }
            cpa_commit();
        }

        // ---- mma chunk i ----
        unsigned* bHi = smem + OFF_B + s * ABUF;
        unsigned* bLo = bHi + 2304;
        #pragma unroll
        for (int ks = 0; ks < 4; ks++) {
            int base = (m0 + g) * ASTR + (ks << 3) + tg;
            unsigned ah0 = aHi[base],            ah2 = aHi[base + 4];
            unsigned ah1 = aHi[base + 8 * ASTR], ah3 = aHi[base + 8 * ASTR + 4];
            unsigned al0 = aLo[base],            al2 = aLo[base + 4];
            unsigned al1 = aLo[base + 8 * ASTR], al3 = aLo[base + 8 * ASTR + 4];
            #pragma unroll
            for (int nt = 0; nt < 4; nt++) {
                int bidx = ((ks << 3) + tg) * BSTR + n0 + (nt << 3) + g;
                unsigned bh0 = bHi[bidx], bh1 = bHi[bidx + 4 * BSTR];
                unsigned bl0 = bLo[bidx], bl1 = bLo[bidx + 4 * BSTR];
                mma_bf16(aM[nt], ah0, ah1, ah2, ah3, bh0, bh1);
                mma_bf16(aC[nt], al0, al1, al2, al3, bh0, bh1);
                mma_bf16(aC[nt], ah0, ah1, ah2, ah3, bl0, bl1);
            }
        }
    }

    // ---- epilogue 1: bias + GELU -> packed H tile ----
    unsigned* sHhi = smem + OFF_H;
    unsigned* sHlo = sHhi + 2304;
    #pragma unroll
    for (int nt = 0; nt < 4; nt++) {
        float2 bb = *(const float2*)(b1 + n0 + (nt << 3) + (tg << 1));
        float v0 = gelu(aM[nt][0] + aC[nt][0] + bb.x);
        float v1 = gelu(aM[nt][1] + aC[nt][1] + bb.y);
        float v2 = gelu(aM[nt][2] + aC[nt][2] + bb.x);
        float v3 = gelu(aM[nt][3] + aC[nt][3] + bb.y);
        int hp = (n0 >> 1) + (nt << 2) + tg;
        unsigned ph, pl;
        bsplit(v0, v1, ph, pl);
        sHhi[(m0 + g) * HSTR + hp] = ph; sHlo[(m0 + g) * HSTR + hp] = pl;
        bsplit(v2, v3, ph, pl);
        sHhi[(m0 + g + 8) * HSTR + hp] = ph; sHlo[(m0 + g + 8) * HSTR + hp] = pl;
    }

    cpa_wait0();        // W2 tile (issued at i==9, buf 0) complete
    __syncthreads();    // also publishes sH

    // ---- GEMM2: y = H @ W2 + b2 ----
    unsigned* w2Hi = smem + OFF_B;      // buf 0
    unsigned* w2Lo = w2Hi + 2304;
    float oM[4][4] = {{0,0,0,0},{0,0,0,0},{0,0,0,0},{0,0,0,0}};
    float oC[4][4] = {{0,0,0,0},{0,0,0,0},{0,0,0,0},{0,0,0,0}};
    #pragma unroll
    for (int ks = 0; ks < 4; ks++) {
        int base = (m0 + g) * HSTR + (ks << 3) + tg;
        unsigned ah0 = sHhi[base],            ah2 = sHhi[base + 4];
        unsigned ah1 = sHhi[base + 8 * HSTR], ah3 = sHhi[base + 8 * HSTR + 4];
        unsigned al0 = sHlo[base],            al2 = sHlo[base + 4];
        unsigned al1 = sHlo[base + 8 * HSTR], al3 = sHlo[base + 8 * HSTR + 4];
        #pragma unroll
        for (int nt = 0; nt < 4; nt++) {
            int bidx = ((ks << 3) + tg) * BSTR + n0 + (nt << 3) + g;
            unsigned bh0 = w2Hi[bidx], bh1 = w2Hi[bidx + 4 * BSTR];
            unsigned bl0 = w2Lo[bidx], bl1 = w2Lo[bidx + 4 * BSTR];
            mma_bf16(oM[nt], ah0, ah1, ah2, ah3, bh0, bh1);
            mma_bf16(oC[nt], al0, al1, al2, al3, bh0, bh1);
            mma_bf16(oC[nt], ah0, ah1, ah2, ah3, bl0, bl1);
        }
    }

    // ---- epilogue 2: bias + store ----
    const size_t pixbase = (((size_t)((b << 7) + h)) << 7) + w0;
    #pragma unroll
    for (int nt = 0; nt < 4; nt++) {
        int col = n0 + (nt << 3) + (tg << 1);
        float2 bb = *(const float2*)(b2 + col);
        *(float2*)(y + ((pixbase + m0 + g) << 6) + col) =
            make_float2(oM[nt][0] + oC[nt][0] + bb.x, oM[nt][1] + oC[nt][1] + bb.y);
        *(float2*)(y + ((pixbase + m0 + g + 8) << 6) + col) =
            make_float2(oM[nt][2] + oC[nt][2] + bb.x, oM[nt][3] + oC[nt][3] + bb.y);
    }
}

// ---------------------------------------------------------------------------
extern "C" void kernel_launch(void* const* d_in, const int* in_sizes, int n_in,
                              void* d_out, int out_size)
{
    const float* x   = (const float*)d_in[0];
    const float* c   = (const float*)d_in[1];
    const float* Wv  = (const float*)d_in[6];
    const float* bv  = (const float*)d_in[7];
    const float* Wo  = (const float*)d_in[8];
    const float* bo  = (const float*)d_in[9];
    const float* lng = (const float*)d_in[10];
    const float* lnb = (const float*)d_in[11];
    const float* pk  = (const float*)d_in[12];
    const float* W1  = (const float*)d_in[13];
    const float* b1  = (const float*)d_in[14];
    const float* W2  = (const float*)d_in[15];
    const float* b2  = (const float*)d_in[16];

    float* y     = (float*)d_out;
    float* outc2 = y + (size_t)8 * 128 * 128 * 64;

    prep_kernel<<<80, THREADS>>>(W1, W2);
    ctx_kernel<<<1, 256>>>(c, Wv, bv, Wo, bo, lng, lnb, outc2);

    cudaFuncSetAttribute(nca_kernel, cudaFuncAttributeMaxDynamicSharedMemorySize, SMEM_BYTES);
    nca_kernel<<<8 * 128 * 2, THREADS, SMEM_BYTES>>>(x, pk, b1, b2, y);
}

// round 6
// speedup vs baseline: 1.3589x; 1.3589x over previous
#include <cuda_runtime.h>
#include <math.h>
#include <stdint.h>

#define THREADS 256
#define USTR2 648      // u32 per U row: 320 kpairs x (hi,lo) + 8 pad ; 324%32==4
#define BSTR2 136      // u32 per W kpair row: 64 n x (hi,lo) + 8 pad ; 68%32==4
#define HSTR2 72       // u32 per H row: 32 kpairs x (hi,lo) + 8 pad ; 36%32==4

// smem layout (u32)
#define OFF_U  0
#define OFF_W  20736
#define WBUF   2176            // one 16-kpair W chunk buffer
#define OFF_H  25088
#define OFF_C2 27392
#define SMEM_U32 27456
#define SMEM_BYTES (SMEM_U32 * 4)   // 109824 B -> 2 CTAs/SM

__device__ float g_c2[8 * 64];
// W1 pre-split + interleaved: [chunk 0..19][kpair 0..15][n 0..63][hi,lo]
__device__ __align__(16) unsigned gW1p[20 * 2048];
// W2: [kpair 0..31][n][hi,lo]
__device__ __align__(16) unsigned gW2p[4096];

// ---------------------------------------------------------------------------
__device__ __forceinline__ unsigned s2u(const void* p) {
    unsigned a;
    asm("{ .reg .u64 t; cvta.to.shared.u64 t, %1; cvt.u32.u64 %0, t; }" : "=r"(a) : "l"(p));
    return a;
}

// pack pair (e = even k, o = odd k) -> bf16x2 hi + bf16x2 lo residual
__device__ __forceinline__ void bsplit(float e, float o, unsigned& ph, unsigned& pl) {
    asm("cvt.rn.bf16x2.f32 %0, %1, %2;" : "=r"(ph) : "f"(o), "f"(e));
    float eh = __uint_as_float(ph << 16);
    float oh = __uint_as_float(ph & 0xffff0000u);
    asm("cvt.rn.bf16x2.f32 %0, %1, %2;" : "=r"(pl) : "f"(o - oh), "f"(e - eh));
}

__device__ __forceinline__ void mma_bf16(float* c,
                                         unsigned a0, unsigned a1, unsigned a2, unsigned a3,
                                         unsigned b0, unsigned b1)
{
    asm volatile(
        "mma.sync.aligned.m16n8k16.row.col.f32.bf16.bf16.f32 "
        "{%0,%1,%2,%3}, {%4,%5,%6,%7}, {%8,%9}, {%0,%1,%2,%3};"
        : "+f"(c[0]), "+f"(c[1]), "+f"(c[2]), "+f"(c[3])
        : "r"(a0), "r"(a1), "r"(a2), "r"(a3), "r"(b0), "r"(b1));
}

__device__ __forceinline__ float gelu(float v) {
    return 0.5f * v * (1.0f + erff(v * 0.70710678118654752440f));
}

__device__ __forceinline__ void cpa16(unsigned dst, const void* src) {
    asm volatile("cp.async.ca.shared.global [%0], [%1], 16;" :: "r"(dst), "l"(src));
}
__device__ __forceinline__ void cpa_commit() {
    asm volatile("cp.async.commit_group;" ::: "memory");
}
__device__ __forceinline__ void cpa_wait0() {
    asm volatile("cp.async.wait_group 0;" ::: "memory");
}

// ---------------------------------------------------------------------------
// prep (blocks 0..79): split W1/W2 -> interleaved hi/lo pair tiles.
// ctx (block 80): attention collapses analytically (softmax pooling of a
// spatially constant value == the value). c2 = c + LN((c@Wv+bv)@Wo + bo + c).
// ---------------------------------------------------------------------------
__global__ void prep_ctx_kernel(const float* __restrict__ W1, const float* __restrict__ W2,
                                const float* __restrict__ c,
                                const float* __restrict__ Wv, const float* __restrict__ bv,
                                const float* __restrict__ Wo, const float* __restrict__ bo,
                                const float* __restrict__ lng, const float* __restrict__ lnb,
                                float* __restrict__ outc2)
{
    if (blockIdx.x < 80) {
        int t = blockIdx.x * THREADS + threadIdx.x;
        if (t < 20 * 1024) {
            int ch = t >> 10, kp = (t >> 6) & 15, n = t & 63;
            int k = ch * 32 + 2 * kp;
            unsigned ph, pl;
            bsplit(W1[k * 64 + n], W1[(k + 1) * 64 + n], ph, pl);
            gW1p[2 * t] = ph; gW1p[2 * t + 1] = pl;
        }
        if (t < 2048) {
            int kp = t >> 6, n = t & 63;
            unsigned ph, pl;
            bsplit(W2[(2 * kp) * 64 + n], W2[(2 * kp + 1) * 64 + n], ph, pl);
            gW2p[2 * t] = ph; gW2p[2 * t + 1] = pl;
        }
        return;
    }
    __shared__ float sv[8][64];
    __shared__ float st[8][64];
    int b = threadIdx.x >> 5;
    int lane = threadIdx.x & 31;

    #pragma unroll
    for (int oo = 0; oo < 2; oo++) {
        int o = lane + 32 * oo;
        float acc = bv[o];
        #pragma unroll 8
        for (int i = 0; i < 64; i++) acc += c[b * 64 + i] * Wv[i * 64 + o];
        sv[b][o] = acc;
    }
    __syncwarp();
    #pragma unroll
    for (int oo = 0; oo < 2; oo++) {
        int o = lane + 32 * oo;
        float acc = bo[o] + c[b * 64 + o];
        #pragma unroll 8
        for (int i = 0; i < 64; i++) acc += sv[b][i] * Wo[i * 64 + o];
        st[b][o] = acc;
    }
    __syncwarp();
    float t0 = st[b][lane], t1 = st[b][lane + 32];
    float s = t0 + t1;
    #pragma unroll
    for (int off = 16; off; off >>= 1) s += __shfl_xor_sync(0xffffffffu, s, off);
    float m = s * (1.0f / 64.0f);
    float d0 = t0 - m, d1 = t1 - m;
    float q = d0 * d0 + d1 * d1;
    #pragma unroll
    for (int off = 16; off; off >>= 1) q += __shfl_xor_sync(0xffffffffu, q, off);
    float inv = rsqrtf(q * (1.0f / 64.0f) + 1e-5f);
    #pragma unroll
    for (int oo = 0; oo < 2; oo++) {
        int o = lane + 32 * oo;
        float a = (st[b][o] - m) * inv * lng[o] + lnb[o];
        float v2 = c[b * 64 + o] + a;
        g_c2[b * 64 + o] = v2;
        outc2[b * 64 + o] = v2;
    }
}

// ---------------------------------------------------------------------------
// main: 32-px blocks. Phase 1 materializes packed U (max MLP). GEMM1 streams
// 20 x 32-k chunks with cp.async double-buffered W. All frags via LDS.64.
// ---------------------------------------------------------------------------
__global__ __launch_bounds__(256, 2)
void nca_kernel(const float* __restrict__ x, const float* __restrict__ pk,
                const float* __restrict__ b1, const float* __restrict__ b2,
                float* __restrict__ y)
{
    extern __shared__ unsigned smem[];
    unsigned sbase = s2u(smem);
    unsigned* sU = smem + OFF_U;
    unsigned* sH = smem + OFF_H;
    float* sC2 = (float*)(smem + OFF_C2);

    int tid = threadIdx.x;
    int warp = tid >> 5, lane = tid & 31;
    int g = lane >> 2, tg = lane & 3;
    int m0 = (warp & 1) << 4;
    int n0 = (warp >> 1) << 4;

    int bi = blockIdx.x;
    int w0 = (bi & 3) << 5;
    int h  = (bi >> 2) & 127;
    int b  = bi >> 9;

    const size_t imgbase = ((size_t)((b << 7) + h)) << 13;
    int skp = tid >> 4, sq = tid & 15;   // staging: kpair row, 8-u32 quad

    // prefetch W chunk 0 (overlaps with all of phase 1)
    {
        unsigned d = sbase + (OFF_W + skp * BSTR2 + sq * 8) * 4;
        const unsigned* s = gW1p + skp * 128 + sq * 8;
        cpa16(d, s); cpa16(d + 16, s + 4);
    }
    cpa_commit();
    if (tid < 64) sC2[tid] = g_c2[b * 64 + tid];
    __syncthreads();

    // ---- phase 1a: x copy (kpairs 0-31) + c2 broadcast (kpairs 32-63) ----
    #pragma unroll
    for (int j = 0; j < 8; j++) {
        int item = (j << 8) + tid;
        int pr = item & 63;
        int p  = item >> 6;
        float2 v;
        if (pr < 32) {
            v = *(const float2*)(x + imgbase + ((size_t)(w0 + p) << 6) + (pr << 1));
        } else {
            v = make_float2(sC2[(pr - 32) << 1], sC2[((pr - 32) << 1) + 1]);
        }
        unsigned ph, pl; bsplit(v.x, v.y, ph, pl);
        *(uint2*)&sU[p * USTR2 + pr * 2] = make_uint2(ph, pl);
    }

    // ---- phase 1b: context half (conv of constant = c2 * masked tap sums) ----
    {
        int cpair = tid >> 1, half = tid & 1;
        int di = cpair >> 5, cq = cpair & 31;
        int ch = 64 + (cq << 1);
        int d  = 1 << di;
        int pc = 96 + (di << 6) + cq;
        const float* tp = pk + ((di << 7) + ch) * 9;
        float cs0[3] = {0, 0, 0}, cs1[3] = {0, 0, 0};
        #pragma unroll
        for (int t3 = 0; t3 < 3; t3++) {
            int hh = h + (t3 - 1) * d;
            if ((unsigned)hh < 128u) {
                #pragma unroll
                for (int dx = 0; dx < 3; dx++) {
                    cs0[dx] += tp[t3 * 3 + dx];
                    cs1[dx] += tp[9 + t3 * 3 + dx];
                }
            }
        }
        float c0 = sC2[ch - 64], c1 = sC2[ch - 63];
        #pragma unroll
        for (int j = 0; j < 16; j++) {
            int p = (j << 1) + half;
            int w = w0 + p;
            float k0 = 0.f, k1 = 0.f;
            #pragma unroll
            for (int dx = 0; dx < 3; dx++) {
                int ww = w + (dx - 1) * d;
                if ((unsigned)ww < 128u) { k0 += cs0[dx]; k1 += cs1[dx]; }
            }
            unsigned ph, pl; bsplit(c0 * k0, c1 * k1, ph, pl);
            *(uint2*)&sU[p * USTR2 + pc * 2] = make_uint2(ph, pl);
        }
    }

    // ---- phase 1c: real depthwise dilated conv (x half) ----
    {
        int cpair = tid >> 1, half = tid & 1;
        int di = cpair >> 5, chp = cpair & 31;
        int ch = chp << 1;
        int d  = 1 << di;
        int pc = 64 + (di << 6) + chp;
        const float* tp = pk + ((di << 7) + ch) * 9;
        float tap0[9], tap1[9];
        #pragma unroll
        for (int t9 = 0; t9 < 9; t9++) { tap0[t9] = tp[t9]; tap1[t9] = tp[9 + t9]; }
        const float* rp[3]; bool rv[3];
        #pragma unroll
        for (int t3 = 0; t3 < 3; t3++) {
            int hh = h + (t3 - 1) * d;
            rv[t3] = ((unsigned)hh < 128u);
            rp[t3] = x + (((size_t)((b << 7) + (hh & 127))) << 13) + ch;
        }
        #pragma unroll 4
        for (int j = 0; j < 16; j++) {
            int p = (j << 1) + half;
            int w = w0 + p;
            float a0 = 0.f, a1 = 0.f;
            #pragma unroll
            for (int t3 = 0; t3 < 3; t3++) {
                if (rv[t3]) {
                    #pragma unroll
                    for (int dx = 0; dx < 3; dx++) {
                        int ww = w + (dx - 1) * d;
                        if ((unsigned)ww < 128u) {
                            float2 v = *(const float2*)(rp[t3] + ((size_t)ww << 6));
                            a0 += v.x * tap0[t3 * 3 + dx];
                            a1 += v.y * tap1[t3 * 3 + dx];
                        }
                    }
                }
            }
            unsigned ph, pl; bsplit(a0, a1, ph, pl);
            *(uint2*)&sU[p * USTR2 + pc * 2] = make_uint2(ph, pl);
        }
    }
    __syncthreads();

    // ---- GEMM1: 20 chunks of 32 k, double-buffered W via cp.async ----
    float aM[2][4] = {{0,0,0,0},{0,0,0,0}};
    float aC[2][4] = {{0,0,0,0},{0,0,0,0}};

    for (int i = 0; i < 20; i++) {
        int s = i & 1;
        cpa_wait0();
        __syncthreads();
        // prefetch next chunk (or W2 first half) into buf s^1
        {
            const unsigned* src = (i < 19) ? (gW1p + (i + 1) * 2048) : gW2p;
            unsigned d = sbase + (OFF_W + (s ^ 1) * WBUF + skp * BSTR2 + sq * 8) * 4;
            const unsigned* sp = src + skp * 128 + sq * 8;
            cpa16(d, sp); cpa16(d + 16, sp + 4);
            cpa_commit();
        }
        unsigned* bW = smem + OFF_W + s * WBUF;
        #pragma unroll
        for (int ks = 0; ks < 2; ks++) {
            int arow = (m0 + g) * USTR2 + (i * 16 + ks * 8 + tg) * 2;
            uint2 a0 = *(uint2*)&sU[arow];
            uint2 a1 = *(uint2*)&sU[arow + 8 * USTR2];
            uint2 a2 = *(uint2*)&sU[arow + 8];
            uint2 a3 = *(uint2*)&sU[arow + 8 * USTR2 + 8];
            #pragma unroll
            for (int nt = 0; nt < 2; nt++) {
                int bidx = (ks * 8 + tg) * BSTR2 + (n0 + nt * 8 + g) * 2;
                uint2 b0 = *(uint2*)&bW[bidx];
                uint2 b1 = *(uint2*)&bW[bidx + 4 * BSTR2];
                mma_bf16(aM[nt], a0.x, a1.x, a2.x, a3.x, b0.x, b1.x);
                mma_bf16(aC[nt], a0.y, a1.y, a2.y, a3.y, b0.x, b1.x);
                mma_bf16(aC[nt], a0.x, a1.x, a2.x, a3.x, b0.y, b1.y);
            }
        }
    }

    // ---- epilogue 1: bias + GELU; stage W2 second half; write H ----
    float hv[2][4];
    #pragma unroll
    for (int nt = 0; nt < 2; nt++) {
        float2 bb = *(const float2*)(b1 + n0 + (nt << 3) + (tg << 1));
        hv[nt][0] = gelu(aM[nt][0] + aC[nt][0] + bb.x);
        hv[nt][1] = gelu(aM[nt][1] + aC[nt][1] + bb.y);
        hv[nt][2] = gelu(aM[nt][2] + aC[nt][2] + bb.x);
        hv[nt][3] = gelu(aM[nt][3] + aC[nt][3] + bb.y);
    }
    cpa_wait0();        // W2 first half landed (buf 0)
    __syncthreads();    // all warps done with buf 1 (chunk 19)
    {
        unsigned d = sbase + (OFF_W + WBUF + skp * BSTR2 + sq * 8) * 4;
        const unsigned* sp = gW2p + 2048 + skp * 128 + sq * 8;
        cpa16(d, sp); cpa16(d + 16, sp + 4);
        cpa_commit();
    }
    #pragma unroll
    for (int nt = 0; nt < 2; nt++) {
        int hp = (n0 >> 1) + (nt << 2) + tg;
        unsigned ph, pl;
        bsplit(hv[nt][0], hv[nt][1], ph, pl);
        *(uint2*)&sH[(m0 + g) * HSTR2 + hp * 2] = make_uint2(ph, pl);
        bsplit(hv[nt][2], hv[nt][3], ph, pl);
        *(uint2*)&sH[(m0 + g + 8) * HSTR2 + hp * 2] = make_uint2(ph, pl);
    }
    cpa_wait0();
    __syncthreads();

    // ---- GEMM2: y = H @ W2 + b2 (W2 = 32 kpairs contiguous at OFF_W) ----
    unsigned* bW2 = smem + OFF_W;
    float oM[2][4] = {{0,0,0,0},{0,0,0,0}};
    float oC[2][4] = {{0,0,0,0},{0,0,0,0}};
    #pragma unroll
    for (int ks = 0; ks < 4; ks++) {
        int arow = (m0 + g) * HSTR2 + (ks * 8 + tg) * 2;
        uint2 a0 = *(uint2*)&sH[arow];
        uint2 a1 = *(uint2*)&sH[arow + 8 * HSTR2];
        uint2 a2 = *(uint2*)&sH[arow + 8];
        uint2 a3 = *(uint2*)&sH[arow + 8 * HSTR2 + 8];
        #pragma unroll
        for (int nt = 0; nt < 2; nt++) {
            int bidx = (ks * 8 + tg) * BSTR2 + (n0 + nt * 8 + g) * 2;
            uint2 b0 = *(uint2*)&bW2[bidx];
            uint2 b1 = *(uint2*)&bW2[bidx + 4 * BSTR2];
            mma_bf16(oM[nt], a0.x, a1.x, a2.x, a3.x, b0.x, b1.x);
            mma_bf16(oC[nt], a0.y, a1.y, a2.y, a3.y, b0.x, b1.x);
            mma_bf16(oC[nt], a0.x, a1.x, a2.x, a3.x, b0.y, b1.y);
        }
    }

    // ---- epilogue 2: bias + store ----
    const size_t pixbase = (((size_t)((b << 7) + h)) << 7) + w0;
    #pragma unroll
    for (int nt = 0; nt < 2; nt++) {
        int col = n0 + (nt << 3) + (tg << 1);
        float2 bb = *(const float2*)(b2 + col);
        *(float2*)(y + ((pixbase + m0 + g) << 6) + col) =
            make_float2(oM[nt][0] + oC[nt][0] + bb.x, oM[nt][1] + oC[nt][1] + bb.y);
        *(float2*)(y + ((pixbase + m0 + g + 8) << 6) + col) =
            make_float2(oM[nt][2] + oC[nt][2] + bb.x, oM[nt][3] + oC[nt][3] + bb.y);
    }
}

// ---------------------------------------------------------------------------
extern "C" void kernel_launch(void* const* d_in, const int* in_sizes, int n_in,
                              void* d_out, int out_size)
{
    const float* x   = (const float*)d_in[0];
    const float* c   = (const float*)d_in[1];
    const float* Wv  = (const float*)d_in[6];
    const float* bv  = (const float*)d_in[7];
    const float* Wo  = (const float*)d_in[8];
    const float* bo  = (const float*)d_in[9];
    const float* lng = (const float*)d_in[10];
    const float* lnb = (const float*)d_in[11];
    const float* pk  = (const float*)d_in[12];
    const float* W1  = (const float*)d_in[13];
    const float* b1  = (const float*)d_in[14];
    const float* W2  = (const float*)d_in[15];
    const float* b2  = (const float*)d_in[16];

    float* y     = (float*)d_out;
    float* outc2 = y + (size_t)8 * 128 * 128 * 64;

    prep_ctx_kernel<<<81, THREADS>>>(W1, W2, c, Wv, bv, Wo, bo, lng, lnb, outc2);

    cudaFuncSetAttribute(nca_kernel, cudaFuncAttributeMaxDynamicSharedMemorySize, SMEM_BYTES);
    nca_kernel<<<4096, THREADS, SMEM_BYTES>>>(x, pk, b1, b2, y);
}

// round 9
// speedup vs baseline: 1.4337x; 1.0551x over previous
#include <cuda_runtime.h>
#include <math.h>
#include <stdint.h>

#define THREADS 256

// smem layout (u32 units)
#define OFF_U   0          // sUhi [32][324]
#define ULO     10368      // sUlo
#define OFF_W   20736      // 2 bufs x (hi [64][20] + lo [64][20])
#define WBUF    2560
#define WLO     1280
#define OFF_H   25856      // Hhi [32][36] + Hlo
#define HLO     1152
#define OFF_C2  28160
#define SMEM_U32 28224
#define SMEM_BYTES (SMEM_U32 * 4)   // 112896 B -> 2 CTAs/SM

#define USTR 324   // row stride 1296B == 16 mod 128 -> ldmatrix conflict-free
#define BSTR 20    // row stride 80B: 8-row segments rotate over all 32 banks
#define HSTR 36    // row stride 144B == 16 mod 128

__device__ float g_c2[8 * 64];
// W1 n-major bf16x2 pair tiles: [chunk 0..19][hi/lo][n 0..63][kpair 0..15]
__device__ __align__(16) unsigned gW1n[20 * 2048];
// W2: [hi/lo][n 0..63][kpair 0..31]
__device__ __align__(16) unsigned gW2n[4096];

// ---------------------------------------------------------------------------
__device__ __forceinline__ unsigned s2u(const void* p) {
    unsigned a;
    asm("{ .reg .u64 t; cvta.to.shared.u64 t, %1; cvt.u32.u64 %0, t; }" : "=r"(a) : "l"(p));
    return a;
}

// pack pair (e = even k, o = odd k) -> bf16x2 hi + bf16x2 lo residual
__device__ __forceinline__ void bsplit(float e, float o, unsigned& ph, unsigned& pl) {
    asm("cvt.rn.bf16x2.f32 %0, %1, %2;" : "=r"(ph) : "f"(o), "f"(e));
    float eh = __uint_as_float(ph << 16);
    float oh = __uint_as_float(ph & 0xffff0000u);
    asm("cvt.rn.bf16x2.f32 %0, %1, %2;" : "=r"(pl) : "f"(o - oh), "f"(e - eh));
}

__device__ __forceinline__ void mma_bf16(float* c,
                                         unsigned a0, unsigned a1, unsigned a2, unsigned a3,
                                         unsigned b0, unsigned b1)
{
    asm volatile(
        "mma.sync.aligned.m16n8k16.row.col.f32.bf16.bf16.f32 "
        "{%0,%1,%2,%3}, {%4,%5,%6,%7}, {%8,%9}, {%0,%1,%2,%3};"
        : "+f"(c[0]), "+f"(c[1]), "+f"(c[2]), "+f"(c[3])
        : "r"(a0), "r"(a1), "r"(a2), "r"(a3), "r"(b0), "r"(b1));
}

#define LDSM4(r0, r1, r2, r3, addr) \
    asm volatile("ldmatrix.sync.aligned.m8n8.x4.shared.b16 {%0,%1,%2,%3}, [%4];" \
                 : "=r"(r0), "=r"(r1), "=r"(r2), "=r"(r3) : "r"(addr))

__device__ __forceinline__ float gelu(float v) {
    return 0.5f * v * (1.0f + erff(v * 0.70710678118654752440f));
}

__device__ __forceinline__ void cpa16(unsigned dst, const void* src) {
    asm volatile("cp.async.ca.shared.global [%0], [%1], 16;" :: "r"(dst), "l"(src));
}
__device__ __forceinline__ void cpa_commit() {
    asm volatile("cp.async.commit_group;" ::: "memory");
}
__device__ __forceinline__ void cpa_wait0() {
    asm volatile("cp.async.wait_group 0;" ::: "memory");
}

// ---------------------------------------------------------------------------
// prep (blocks 0..79): W1/W2 -> n-major hi/lo bf16x2 pair tiles.
// ctx (block 80): attention collapses analytically (softmax pooling of a
// spatially constant value == the value). c2 = c + LN((c@Wv+bv)@Wo + bo + c).
// ---------------------------------------------------------------------------
__global__ void prep_ctx_kernel(const float* __restrict__ W1, const float* __restrict__ W2,
                                const float* __restrict__ c,
                                const float* __restrict__ Wv, const float* __restrict__ bv,
                                const float* __restrict__ Wo, const float* __restrict__ bo,
                                const float* __restrict__ lng, const float* __restrict__ lnb,
                                float* __restrict__ outc2)
{
    if (blockIdx.x < 80) {
        int t = blockIdx.x * THREADS + threadIdx.x;
        {   // W1: t in [0, 20480)
            int ch = t >> 10, n = (t >> 4) & 63, kp = t & 15;
            int k = ch * 32 + 2 * kp;
            unsigned ph, pl;
            bsplit(W1[k * 64 + n], W1[(k + 1) * 64 + n], ph, pl);
            gW1n[ch * 2048 + n * 16 + kp] = ph;
            gW1n[ch * 2048 + 1024 + n * 16 + kp] = pl;
        }
        if (t < 2048) {
            int n = t >> 5, kp = t & 31;
            unsigned ph, pl;
            bsplit(W2[(2 * kp) * 64 + n], W2[(2 * kp + 1) * 64 + n], ph, pl);
            gW2n[n * 32 + kp] = ph;
            gW2n[2048 + n * 32 + kp] = pl;
        }
        return;
    }
    __shared__ float sv[8][64];
    __shared__ float st[8][64];
    int b = threadIdx.x >> 5;
    int lane = threadIdx.x & 31;

    #pragma unroll
    for (int oo = 0; oo < 2; oo++) {
        int o = lane + 32 * oo;
        float acc = bv[o];
        #pragma unroll 8
        for (int i = 0; i < 64; i++) acc += c[b * 64 + i] * Wv[i * 64 + o];
        sv[b][o] = acc;
    }
    __syncwarp();
    #pragma unroll
    for (int oo = 0; oo < 2; oo++) {
        int o = lane + 32 * oo;
        float acc = bo[o] + c[b * 64 + o];
        #pragma unroll 8
        for (int i = 0; i < 64; i++) acc += sv[b][i] * Wo[i * 64 + o];
        st[b][o] = acc;
    }
    __syncwarp();
    float t0 = st[b][lane], t1 = st[b][lane + 32];
    float s = t0 + t1;
    #pragma unroll
    for (int off = 16; off; off >>= 1) s += __shfl_xor_sync(0xffffffffu, s, off);
    float m = s * (1.0f / 64.0f);
    float d0 = t0 - m, d1 = t1 - m;
    float q = d0 * d0 + d1 * d1;
    #pragma unroll
    for (int off = 16; off; off >>= 1) q += __shfl_xor_sync(0xffffffffu, q, off);
    float inv = rsqrtf(q * (1.0f / 64.0f) + 1e-5f);
    #pragma unroll
    for (int oo = 0; oo < 2; oo++) {
        int o = lane + 32 * oo;
        float a = (st[b][o] - m) * inv * lng[o] + lnb[o];
        float v2 = c[b * 64 + o] + a;
        g_c2[b * 64 + o] = v2;
        outc2[b * 64 + o] = v2;
    }
}

// ---------------------------------------------------------------------------
// main: 32-px blocks, full U in smem (hi/lo tiles), all GEMM fragments via
// ldmatrix.x4, cp.async double-buffered W1 stream, W2 staged into dead U.
// ---------------------------------------------------------------------------
__global__ __launch_bounds__(256, 2)
void nca_kernel(const float* __restrict__ x, const float* __restrict__ pk,
                const float* __restrict__ b1, const float* __restrict__ b2,
                float* __restrict__ y)
{
    extern __shared__ unsigned smem[];
    unsigned sbase = s2u(smem);
    unsigned* sUhi = smem + OFF_U;
    unsigned* sUlo = smem + ULO;
    float* sC2 = (float*)(smem + OFF_C2);

    int tid = threadIdx.x;
    int warp = tid >> 5, lane = tid & 31;
    int g = lane >> 2, tg = lane & 3;
    int m0 = (warp & 1) << 4;
    int n0 = (warp >> 1) << 4;

    int bi = blockIdx.x;
    int w0 = (bi & 3) << 5;
    int h  = (bi >> 2) & 127;
    int b  = bi >> 9;

    const size_t imgbase = ((size_t)((b << 7) + h)) << 13;

    // ---- prefetch W1 chunk 0 (overlaps all of phase 1) ----
    #pragma unroll
    for (int j = 0; j < 2; j++) {
        int idx = tid + (j << 8);
        int half = idx >> 8, r = (idx >> 2) & 63, q = idx & 3;
        cpa16(sbase + (OFF_W + half * WLO + r * BSTR + q * 4) * 4,
              gW1n + half * 1024 + r * 16 + q * 4);
    }
    cpa_commit();
    if (tid < 64) sC2[tid] = g_c2[b * 64 + tid];
    __syncthreads();

    // ---- phase 1a: x copy (kpairs 0-31) + c2 broadcast (kpairs 32-63) ----
    #pragma unroll
    for (int j = 0; j < 8; j++) {
        int item = (j << 8) + tid;
        int pr = item & 63;
        int p  = item >> 6;
        float2 v;
        if (pr < 32) {
            v = *(const float2*)(x + imgbase + ((size_t)(w0 + p) << 6) + (pr << 1));
        } else {
            v = make_float2(sC2[(pr - 32) << 1], sC2[((pr - 32) << 1) + 1]);
        }
        unsigned ph, pl; bsplit(v.x, v.y, ph, pl);
        sUhi[p * USTR + pr] = ph;
        sUlo[p * USTR + pr] = pl;
    }

    // ---- phase 1b: context half (conv of constant = c2 * masked tap sums) ----
    {
        int cpair = tid >> 1, half = tid & 1;
        int di = cpair >> 5, cq = cpair & 31;
        int ch = 64 + (cq << 1);
        int d  = 1 << di;
        int pc = 96 + (di << 6) + cq;
        const float* tp = pk + ((di << 7) + ch) * 9;
        float cs0[3] = {0, 0, 0}, cs1[3] = {0, 0, 0};
        #pragma unroll
        for (int t3 = 0; t3 < 3; t3++) {
            int hh = h + (t3 - 1) * d;
            if ((unsigned)hh < 128u) {
                #pragma unroll
                for (int dx = 0; dx < 3; dx++) {
                    cs0[dx] += tp[t3 * 3 + dx];
                    cs1[dx] += tp[9 + t3 * 3 + dx];
                }
            }
        }
        float c0 = sC2[ch - 64], c1 = sC2[ch - 63];
        #pragma unroll
        for (int j = 0; j < 16; j++) {
            int p = (j << 1) + half;
            int w = w0 + p;
            float k0 = 0.f, k1 = 0.f;
            #pragma unroll
            for (int dx = 0; dx < 3; dx++) {
                int ww = w + (dx - 1) * d;
                if ((unsigned)ww < 128u) { k0 += cs0[dx]; k1 += cs1[dx]; }
            }
            unsigned ph, pl; bsplit(c0 * k0, c1 * k1, ph, pl);
            sUhi[p * USTR + pc] = ph;
            sUlo[p * USTR + pc] = pl;
        }
    }

    // ---- phase 1c: real depthwise dilated conv (x half) ----
    {
        int cpair = tid >> 1, half = tid & 1;
        int di = cpair >> 5, chp = cpair & 31;
        int ch = chp << 1;
        int d  = 1 << di;
        int pc = 64 + (di << 6) + chp;
        const float* tp = pk + ((di << 7) + ch) * 9;
        float tap0[9], tap1[9];
        #pragma unroll
        for (int t9 = 0; t9 < 9; t9++) { tap0[t9] = tp[t9]; tap1[t9] = tp[9 + t9]; }
        const float* rp[3]; bool rv[3];
        #pragma unroll
        for (int t3 = 0; t3 < 3; t3++) {
            int hh = h + (t3 - 1) * d;
            rv[t3] = ((unsigned)hh < 128u);
            rp[t3] = x + (((size_t)((b << 7) + (hh & 127))) << 13) + ch;
        }
        #pragma unroll 4
        for (int j = 0; j < 16; j++) {
            int p = (j << 1) + half;
            int w = w0 + p;
            float a0 = 0.f, a1 = 0.f;
            #pragma unroll
            for (int t3 = 0; t3 < 3; t3++) {
                if (rv[t3]) {
                    #pragma unroll
                    for (int dx = 0; dx < 3; dx++) {
                        int ww = w + (dx - 1) * d;
                        if ((unsigned)ww < 128u) {
                            float2 v = *(const float2*)(rp[t3] + ((size_t)ww << 6));
                            a0 += v.x * tap0[t3 * 3 + dx];
                            a1 += v.y * tap1[t3 * 3 + dx];
                        }
                    }
                }
            }
            unsigned ph, pl; bsplit(a0, a1, ph, pl);
            sUhi[p * USTR + pc] = ph;
            sUlo[p * USTR + pc] = pl;
        }
    }
    __syncthreads();

    // ---- ldmatrix lane addresses ----
    int lane7 = lane & 7;
    // A: r0=(m0-7,k0-7) r1=(m8-15,k0-7) r2=(m0-7,k8-15) r3=(m8-15,k8-15)
    unsigned rowA = m0 + lane7 + ((lane >> 3) & 1) * 8;
    unsigned kA4  = ((lane >> 4) & 1) * 4;
    unsigned aHiA = sbase + (rowA * USTR + kA4) * 4;
    // B: r0=(n0-7,k0-7) r1=(n0-7,k8-15) r2=(n8-15,k0-7) r3=(n8-15,k8-15)
    unsigned rowB = n0 + lane7 + ((lane >> 4) & 1) * 8;
    unsigned kB4  = ((lane >> 3) & 1) * 4;
    unsigned bA0  = sbase + (OFF_W + rowB * BSTR + kB4) * 4;

    // ---- GEMM1: 20 chunks of 32 k ----
    float aM[2][4] = {{0,0,0,0},{0,0,0,0}};
    float aC[2][4] = {{0,0,0,0},{0,0,0,0}};

    for (int i = 0; i < 20; i++) {
        int s = i & 1;
        cpa_wait0();
        __syncthreads();
        if (i < 19) {
            #pragma unroll
            for (int j = 0; j < 2; j++) {
                int idx = tid + (j << 8);
                int half = idx >> 8, r = (idx >> 2) & 63, q = idx & 3;
                cpa16(sbase + (OFF_W + (s ^ 1) * WBUF + half * WLO + r * BSTR + q * 4) * 4,
                      gW1n + (i + 1) * 2048 + half * 1024 + r * 16 + q * 4);
            }
            cpa_commit();
        }
        unsigned abase = aHiA + i * 64;
        unsigned bbase = bA0 + s * (WBUF * 4);
        #pragma unroll
        for (int ks = 0; ks < 2; ks++) {
            unsigned ah0, ah1, ah2, ah3, al0, al1, al2, al3;
            unsigned bh0, bh1, bh2, bh3, bl0, bl1, bl2, bl3;
            LDSM4(ah0, ah1, ah2, ah3, abase + ks * 32);
            LDSM4(al0, al1, al2, al3, abase + ULO * 4 + ks * 32);
            LDSM4(bh0, bh1, bh2, bh3, bbase + ks * 32);
            LDSM4(bl0, bl1, bl2, bl3, bbase + WLO * 4 + ks * 32);
            mma_bf16(aM[0], ah0, ah1, ah2, ah3, bh0, bh1);
            mma_bf16(aC[0], al0, al1, al2, al3, bh0, bh1);
            mma_bf16(aC[0], ah0, ah1, ah2, ah3, bl0, bl1);
            mma_bf16(aM[1], ah0, ah1, ah2, ah3, bh2, bh3);
            mma_bf16(aC[1], al0, al1, al2, al3, bh2, bh3);
            mma_bf16(aC[1], ah0, ah1, ah2, ah3, bl2, bl3);
        }
    }

    // ---- all warps done with U + W bufs; stage W2 into dead U region ----
    __syncthreads();
    #pragma unroll
    for (int j = 0; j < 4; j++) {
        int idx = tid + (j << 8);
        int half = idx >> 9, r = (idx >> 3) & 63, q = idx & 7;
        cpa16(sbase + (half * 2304 + r * HSTR + q * 4) * 4,
              gW2n + half * 2048 + r * 32 + q * 4);
    }
    cpa_commit();

    // ---- epilogue 1: bias + GELU -> H tiles (overlaps W2 cp.async) ----
    unsigned* sHhi = smem + OFF_H;
    unsigned* sHlo = smem + OFF_H + HLO;
    #pragma unroll
    for (int nt = 0; nt < 2; nt++) {
        float2 bb = *(const float2*)(b1 + n0 + (nt << 3) + (tg << 1));
        float v0 = gelu(aM[nt][0] + aC[nt][0] + bb.x);
        float v1 = gelu(aM[nt][1] + aC[nt][1] + bb.y);
        float v2 = gelu(aM[nt][2] + aC[nt][2] + bb.x);
        float v3 = gelu(aM[nt][3] + aC[nt][3] + bb.y);
        int hp = (n0 >> 1) + (nt << 2) + tg;
        unsigned ph, pl;
        bsplit(v0, v1, ph, pl);
        sHhi[(m0 + g) * HSTR + hp] = ph;
        sHlo[(m0 + g) * HSTR + hp] = pl;
        bsplit(v2, v3, ph, pl);
        sHhi[(m0 + g + 8) * HSTR + hp] = ph;
        sHlo[(m0 + g + 8) * HSTR + hp] = pl;
    }
    cpa_wait0();
    __syncthreads();

    // ---- GEMM2: y = H @ W2 + b2 ----
    unsigned hA = sbase + (OFF_H + rowA * HSTR + kA4) * 4;
    unsigned w2A = sbase + (rowB * HSTR + kB4) * 4;
    float oM[2][4] = {{0,0,0,0},{0,0,0,0}};
    float oC[2][4] = {{0,0,0,0},{0,0,0,0}};
    #pragma unroll
    for (int ks = 0; ks < 4; ks++) {
        unsigned ah0, ah1, ah2, ah3, al0, al1, al2, al3;
        unsigned bh0, bh1, bh2, bh3, bl0, bl1, bl2, bl3;
        LDSM4(ah0, ah1, ah2, ah3, hA + ks * 32);
        LDSM4(al0, al1, al2, al3, hA + HLO * 4 + ks * 32);
        LDSM4(bh0, bh1, bh2, bh3, w2A + ks * 32);
        LDSM4(bl0, bl1, bl2, bl3, w2A + 2304 * 4 + ks * 32);
        mma_bf16(oM[0], ah0, ah1, ah2, ah3, bh0, bh1);
        mma_bf16(oC[0], al0, al1, al2, al3, bh0, bh1);
        mma_bf16(oC[0], ah0, ah1, ah2, ah3, bl0, bl1);
        mma_bf16(oM[1], ah0, ah1, ah2, ah3, bh2, bh3);
        mma_bf16(oC[1], al0, al1, al2, al3, bh2, bh3);
        mma_bf16(oC[1], ah0, ah1, ah2, ah3, bl2, bl3);
    }

    // ---- epilogue 2: bias + store ----
    const size_t pixbase = (((size_t)((b << 7) + h)) << 7) + w0;
    #pragma unroll
    for (int nt = 0; nt < 2; nt++) {
        int col = n0 + (nt << 3) + (tg << 1);
        float2 bb = *(const float2*)(b2 + col);
        *(float2*)(y + ((pixbase + m0 + g) << 6) + col) =
            make_float2(oM[nt][0] + oC[nt][0] + bb.x, oM[nt][1] + oC[nt][1] + bb.y);
        *(float2*)(y + ((pixbase + m0 + g + 8) << 6) + col) =
            make_float2(oM[nt][2] + oC[nt][2] + bb.x, oM[nt][3] + oC[nt][3] + bb.y);
    }
}

// ---------------------------------------------------------------------------
extern "C" void kernel_launch(void* const* d_in, const int* in_sizes, int n_in,
                              void* d_out, int out_size)
{
    const float* x   = (const float*)d_in[0];
    const float* c   = (const float*)d_in[1];
    const float* Wv  = (const float*)d_in[6];
    const float* bv  = (const float*)d_in[7];
    const float* Wo  = (const float*)d_in[8];
    const float* bo  = (const float*)d_in[9];
    const float* lng = (const float*)d_in[10];
    const float* lnb = (const float*)d_in[11];
    const float* pk  = (const float*)d_in[12];
    const float* W1  = (const float*)d_in[13];
    const float* b1  = (const float*)d_in[14];
    const float* W2  = (const float*)d_in[15];
    const float* b2  = (const float*)d_in[16];

    float* y     = (float*)d_out;
    float* outc2 = y + (size_t)8 * 128 * 128 * 64;

    prep_ctx_kernel<<<81, THREADS>>>(W1, W2, c, Wv, bv, Wo, bo, lng, lnb, outc2);

    cudaFuncSetAttribute(nca_kernel, cudaFuncAttributeMaxDynamicSharedMemorySize, SMEM_BYTES);
    nca_kernel<<<4096, THREADS, SMEM_BYTES>>>(x, pk, b1, b2, y);
}

// round 10
// speedup vs baseline: 1.7945x; 1.2516x over previous
#include <cuda_runtime.h>
#include <math.h>
#include <stdint.h>

#define THREADS 256

// smem layout (u32 units)
#define OFF_U   0          // sUhi [32][324]
#define ULO     10368      // sUlo
#define OFF_H   20736      // Hhi [32][36] + Hlo
#define HLO     1152
#define OFF_C2  23040
#define SMEM_U32 23104
#define SMEM_BYTES (SMEM_U32 * 4)   // 92416 B -> 2 CTAs/SM

#define USTR 324   // row stride 1296B == 16 mod 128 -> ldmatrix conflict-free
#define HSTR 36    // row stride 144B  == 16 mod 128

__device__ float g_c2[8 * 64];
// W1 in per-lane mma fragment order: [ks t 0..39][h hi/lo][vp 0..3][lane][4 regs]
__device__ __align__(16) unsigned gW1f[40 * 1024];
// W2 fragment order: [ks t 0..3][h][ng 0..3][lane][4 regs]
__device__ __align__(16) unsigned gW2f[4 * 1024];

// ---------------------------------------------------------------------------
__device__ __forceinline__ unsigned s2u(const void* p) {
    unsigned a;
    asm("{ .reg .u64 t; cvta.to.shared.u64 t, %1; cvt.u32.u64 %0, t; }" : "=r"(a) : "l"(p));
    return a;
}

// pack pair (e = even k, o = odd k) -> bf16x2 hi + bf16x2 lo residual
__device__ __forceinline__ void bsplit(float e, float o, unsigned& ph, unsigned& pl) {
    asm("cvt.rn.bf16x2.f32 %0, %1, %2;" : "=r"(ph) : "f"(o), "f"(e));
    float eh = __uint_as_float(ph << 16);
    float oh = __uint_as_float(ph & 0xffff0000u);
    asm("cvt.rn.bf16x2.f32 %0, %1, %2;" : "=r"(pl) : "f"(o - oh), "f"(e - eh));
}

__device__ __forceinline__ void mma_bf16(float* c,
                                         unsigned a0, unsigned a1, unsigned a2, unsigned a3,
                                         unsigned b0, unsigned b1)
{
    asm volatile(
        "mma.sync.aligned.m16n8k16.row.col.f32.bf16.bf16.f32 "
        "{%0,%1,%2,%3}, {%4,%5,%6,%7}, {%8,%9}, {%0,%1,%2,%3};"
        : "+f"(c[0]), "+f"(c[1]), "+f"(c[2]), "+f"(c[3])
        : "r"(a0), "r"(a1), "r"(a2), "r"(a3), "r"(b0), "r"(b1));
}

#define LDSM4(r0, r1, r2, r3, addr) \
    asm volatile("ldmatrix.sync.aligned.m8n8.x4.shared.b16 {%0,%1,%2,%3}, [%4];" \
                 : "=r"(r0), "=r"(r1), "=r"(r2), "=r"(r3) : "r"(addr))

__device__ __forceinline__ float gelu(float v) {
    return 0.5f * v * (1.0f + erff(v * 0.70710678118654752440f));
}

// ---------------------------------------------------------------------------
// prep (blocks 0..79): W1/W2 -> per-lane mma fragment order, bf16 hi/lo.
// ctx (block 80): attention collapses analytically (softmax pooling of a
// spatially constant value == the value). c2 = c + LN((c@Wv+bv)@Wo + bo + c).
// ---------------------------------------------------------------------------
__global__ void prep_ctx_kernel(const float* __restrict__ W1, const float* __restrict__ W2,
                                const float* __restrict__ c,
                                const float* __restrict__ Wv, const float* __restrict__ bv,
                                const float* __restrict__ Wo, const float* __restrict__ bo,
                                const float* __restrict__ lng, const float* __restrict__ lnb,
                                float* __restrict__ outc2)
{
    if (blockIdx.x < 80) {
        int item = blockIdx.x * THREADS + threadIdx.x;    // 0..20479
        {   // W1 fragments
            int comp = item & 3, lane = (item >> 2) & 31, vp = (item >> 7) & 3, t = item >> 9;
            int g = lane >> 2, tg = lane & 3;
            int v = vp * 2 + (comp >> 1), which = comp & 1;
            int n = v * 8 + g;
            int k0 = t * 16 + tg * 2 + which * 8;
            unsigned ph, pl;
            bsplit(W1[k0 * 64 + n], W1[(k0 + 1) * 64 + n], ph, pl);
            int base = ((t * 8 + vp) * 32 + lane) * 4 + comp;
            gW1f[base] = ph;
            gW1f[base + 512] = pl;
        }
        if (item < 2048) {   // W2 fragments
            int comp = item & 3, lane = (item >> 2) & 31, ng = (item >> 7) & 3, t = item >> 9;
            int g = lane >> 2, tg = lane & 3;
            int v = 2 * ng + (comp >> 1), which = comp & 1;
            int n = v * 8 + g;
            int k0 = t * 16 + tg * 2 + which * 8;
            unsigned ph, pl;
            bsplit(W2[k0 * 64 + n], W2[(k0 + 1) * 64 + n], ph, pl);
            int base = ((t * 8 + ng) * 32 + lane) * 4 + comp;
            gW2f[base] = ph;
            gW2f[base + 512] = pl;
        }
        return;
    }
    __shared__ float sv[8][64];
    __shared__ float st[8][64];
    int b = threadIdx.x >> 5;
    int lane = threadIdx.x & 31;

    #pragma unroll
    for (int oo = 0; oo < 2; oo++) {
        int o = lane + 32 * oo;
        float acc = bv[o];
        #pragma unroll 8
        for (int i = 0; i < 64; i++) acc += c[b * 64 + i] * Wv[i * 64 + o];
        sv[b][o] = acc;
    }
    __syncwarp();
    #pragma unroll
    for (int oo = 0; oo < 2; oo++) {
        int o = lane + 32 * oo;
        float acc = bo[o] + c[b * 64 + o];
        #pragma unroll 8
        for (int i = 0; i < 64; i++) acc += sv[b][i] * Wo[i * 64 + o];
        st[b][o] = acc;
    }
    __syncwarp();
    float t0 = st[b][lane], t1 = st[b][lane + 32];
    float s = t0 + t1;
    #pragma unroll
    for (int off = 16; off; off >>= 1) s += __shfl_xor_sync(0xffffffffu, s, off);
    float m = s * (1.0f / 64.0f);
    float d0 = t0 - m, d1 = t1 - m;
    float q = d0 * d0 + d1 * d1;
    #pragma unroll
    for (int off = 16; off; off >>= 1) q += __shfl_xor_sync(0xffffffffu, q, off);
    float inv = rsqrtf(q * (1.0f / 64.0f) + 1e-5f);
    #pragma unroll
    for (int oo = 0; oo < 2; oo++) {
        int o = lane + 32 * oo;
        float a = (st[b][o] - m) * inv * lng[o] + lnb[o];
        float v2 = c[b * 64 + o] + a;
        g_c2[b * 64 + o] = v2;
        outc2[b * 64 + o] = v2;
    }
}

// ---------------------------------------------------------------------------
// main: 32-px blocks. Phase 1 builds U. GEMM1: warp grid 2m x 4ksplit, WN=64,
// A via ldmatrix (read once), W via direct fragment-order LDG (no smem, no
// barriers). k-split reduced through smem fused with bias+GELU+H pack.
// ---------------------------------------------------------------------------
__global__ __launch_bounds__(256, 2)
void nca_kernel(const float* __restrict__ x, const float* __restrict__ pk,
                const float* __restrict__ b1, const float* __restrict__ b2,
                float* __restrict__ y)
{
    extern __shared__ unsigned smem[];
    unsigned sbase = s2u(smem);
    unsigned* sUhi = smem + OFF_U;
    unsigned* sUlo = smem + ULO;
    float* sC2 = (float*)(smem + OFF_C2);

    int tid = threadIdx.x;
    int warp = tid >> 5, lane = tid & 31;
    int g = lane >> 2, tg = lane & 3;
    int mi = warp & 1;            // m half: rows mi*16 .. mi*16+15
    int kg = warp >> 1;           // k-split group (GEMM1) / n group (GEMM2)
    int m0 = mi << 4;

    int bi = blockIdx.x;
    int w0 = (bi & 3) << 5;
    int h  = (bi >> 2) & 127;
    int b  = bi >> 9;

    const size_t imgbase = ((size_t)((b << 7) + h)) << 13;

    if (tid < 64) sC2[tid] = g_c2[b * 64 + tid];
    __syncthreads();

    // ---- phase 1a: x copy (kpairs 0-31) + c2 broadcast (kpairs 32-63) ----
    #pragma unroll
    for (int j = 0; j < 8; j++) {
        int item = (j << 8) + tid;
        int pr = item & 63;
        int p  = item >> 6;
        float2 v;
        if (pr < 32) {
            v = *(const float2*)(x + imgbase + ((size_t)(w0 + p) << 6) + (pr << 1));
        } else {
            v = make_float2(sC2[(pr - 32) << 1], sC2[((pr - 32) << 1) + 1]);
        }
        unsigned ph, pl; bsplit(v.x, v.y, ph, pl);
        sUhi[p * USTR + pr] = ph;
        sUlo[p * USTR + pr] = pl;
    }

    // ---- phase 1b: context half (conv of constant = c2 * masked tap sums) ----
    {
        int cpair = tid >> 1, half = tid & 1;
        int di = cpair >> 5, cq = cpair & 31;
        int ch = 64 + (cq << 1);
        int d  = 1 << di;
        int pc = 96 + (di << 6) + cq;
        const float* tp = pk + ((di << 7) + ch) * 9;
        float cs0[3] = {0, 0, 0}, cs1[3] = {0, 0, 0};
        #pragma unroll
        for (int t3 = 0; t3 < 3; t3++) {
            int hh = h + (t3 - 1) * d;
            if ((unsigned)hh < 128u) {
                #pragma unroll
                for (int dx = 0; dx < 3; dx++) {
                    cs0[dx] += tp[t3 * 3 + dx];
                    cs1[dx] += tp[9 + t3 * 3 + dx];
                }
            }
        }
        float c0 = sC2[ch - 64], c1 = sC2[ch - 63];
        #pragma unroll
        for (int j = 0; j < 16; j++) {
            int p = (j << 1) + half;
            int w = w0 + p;
            float k0 = 0.f, k1 = 0.f;
            #pragma unroll
            for (int dx = 0; dx < 3; dx++) {
                int ww = w + (dx - 1) * d;
                if ((unsigned)ww < 128u) { k0 += cs0[dx]; k1 += cs1[dx]; }
            }
            unsigned ph, pl; bsplit(c0 * k0, c1 * k1, ph, pl);
            sUhi[p * USTR + pc] = ph;
            sUlo[p * USTR + pc] = pl;
        }
    }

    // ---- phase 1c: real depthwise dilated conv (x half) ----
    {
        int cpair = tid >> 1, half = tid & 1;
        int di = cpair >> 5, chp = cpair & 31;
        int ch = chp << 1;
        int d  = 1 << di;
        int pc = 64 + (di << 6) + chp;
        const float* tp = pk + ((di << 7) + ch) * 9;
        float tap0[9], tap1[9];
        #pragma unroll
        for (int t9 = 0; t9 < 9; t9++) { tap0[t9] = tp[t9]; tap1[t9] = tp[9 + t9]; }
        const float* rp[3]; bool rv[3];
        #pragma unroll
        for (int t3 = 0; t3 < 3; t3++) {
            int hh = h + (t3 - 1) * d;
            rv[t3] = ((unsigned)hh < 128u);
            rp[t3] = x + (((size_t)((b << 7) + (hh & 127))) << 13) + ch;
        }
        #pragma unroll 4
        for (int j = 0; j < 16; j++) {
            int p = (j << 1) + half;
            int w = w0 + p;
            float a0 = 0.f, a1 = 0.f;
            #pragma unroll
            for (int t3 = 0; t3 < 3; t3++) {
                if (rv[t3]) {
                    #pragma unroll
                    for (int dx = 0; dx < 3; dx++) {
                        int ww = w + (dx - 1) * d;
                        if ((unsigned)ww < 128u) {
                            float2 v = *(const float2*)(rp[t3] + ((size_t)ww << 6));
                            a0 += v.x * tap0[t3 * 3 + dx];
                            a1 += v.y * tap1[t3 * 3 + dx];
                        }
                    }
                }
            }
            unsigned ph, pl; bsplit(a0, a1, ph, pl);
            sUhi[p * USTR + pc] = ph;
            sUlo[p * USTR + pc] = pl;
        }
    }
    __syncthreads();

    // ---- ldmatrix lane addresses (A operand) ----
    int lane7 = lane & 7;
    unsigned rowA = m0 + lane7 + ((lane >> 3) & 1) * 8;
    unsigned kA4  = ((lane >> 4) & 1) * 4;
    unsigned aHiA = sbase + (rowA * USTR + kA4) * 4;

    // ---- GEMM1: warp = (mi, kg); k-range = ks-steps kg*10 .. kg*10+9 ----
    float acc[8][4] = {};
    const uint4* __restrict__ w1f = (const uint4*)gW1f;

    #pragma unroll 2
    for (int j = 0; j < 10; j++) {
        int t = kg * 10 + j;
        unsigned ah0, ah1, ah2, ah3, al0, al1, al2, al3;
        LDSM4(ah0, ah1, ah2, ah3, aHiA + t * 32);
        LDSM4(al0, al1, al2, al3, aHiA + ULO * 4 + t * 32);
        const uint4* bp = w1f + t * 256 + lane;
        #pragma unroll
        for (int vp = 0; vp < 4; vp++) {
            uint4 bh = bp[vp * 32];
            uint4 bl = bp[128 + vp * 32];
            mma_bf16(acc[2 * vp],     ah0, ah1, ah2, ah3, bh.x, bh.y);
            mma_bf16(acc[2 * vp],     al0, al1, al2, al3, bh.x, bh.y);
            mma_bf16(acc[2 * vp],     ah0, ah1, ah2, ah3, bl.x, bl.y);
            mma_bf16(acc[2 * vp + 1], ah0, ah1, ah2, ah3, bh.z, bh.w);
            mma_bf16(acc[2 * vp + 1], al0, al1, al2, al3, bh.z, bh.w);
            mma_bf16(acc[2 * vp + 1], ah0, ah1, ah2, ah3, bl.z, bl.w);
        }
    }
    __syncthreads();   // U dead; reduction region aliases it

    // ---- k-split reduction: all warps dump acc (stride-33 rotation) ----
    {
        unsigned* srd = smem + warp * 1056 + lane * 33;
        #pragma unroll
        for (int idx = 0; idx < 32; idx++)
            srd[idx] = __float_as_uint(acc[idx >> 2][idx & 3]);
    }
    __syncthreads();

    // ---- reduce 4 partials + bias + GELU -> H (warp (mi,kg) owns cols kg*16..) ----
    unsigned* sHhi = smem + OFF_H;
    unsigned* sHlo = smem + OFF_H + HLO;
    #pragma unroll
    for (int vv = 0; vv < 2; vv++) {
        int v = 2 * kg + vv;
        float val[4] = {0, 0, 0, 0};
        #pragma unroll
        for (int kq = 0; kq < 4; kq++) {
            const unsigned* srd = smem + (kq * 2 + mi) * 1056 + lane * 33 + v * 4;
            val[0] += __uint_as_float(srd[0]);
            val[1] += __uint_as_float(srd[1]);
            val[2] += __uint_as_float(srd[2]);
            val[3] += __uint_as_float(srd[3]);
        }
        int col = v * 8 + tg * 2;
        float2 bb = *(const float2*)(b1 + col);
        float h0 = gelu(val[0] + bb.x);
        float h1 = gelu(val[1] + bb.y);
        float h2 = gelu(val[2] + bb.x);
        float h3 = gelu(val[3] + bb.y);
        int hp = v * 4 + tg;
        unsigned ph, pl;
        bsplit(h0, h1, ph, pl);
        sHhi[(m0 + g) * HSTR + hp] = ph;
        sHlo[(m0 + g) * HSTR + hp] = pl;
        bsplit(h2, h3, ph, pl);
        sHhi[(m0 + g + 8) * HSTR + hp] = ph;
        sHlo[(m0 + g + 8) * HSTR + hp] = pl;
    }
    __syncthreads();

    // ---- GEMM2: grid 2m x 4n (kg doubles as ng); H via LDSM, W2 via LDG ----
    int n0 = kg << 4;
    unsigned hA = sbase + (OFF_H + rowA * HSTR + kA4) * 4;
    const uint4* __restrict__ w2f = (const uint4*)gW2f;
    float o[2][4] = {};
    #pragma unroll
    for (int t = 0; t < 4; t++) {
        unsigned ah0, ah1, ah2, ah3, al0, al1, al2, al3;
        LDSM4(ah0, ah1, ah2, ah3, hA + t * 32);
        LDSM4(al0, al1, al2, al3, hA + HLO * 4 + t * 32);
        const uint4* bp = w2f + t * 256 + kg * 32 + lane;
        uint4 bh = bp[0];
        uint4 bl = bp[128];
        mma_bf16(o[0], ah0, ah1, ah2, ah3, bh.x, bh.y);
        mma_bf16(o[0], al0, al1, al2, al3, bh.x, bh.y);
        mma_bf16(o[0], ah0, ah1, ah2, ah3, bl.x, bl.y);
        mma_bf16(o[1], ah0, ah1, ah2, ah3, bh.z, bh.w);
        mma_bf16(o[1], al0, al1, al2, al3, bh.z, bh.w);
        mma_bf16(o[1], ah0, ah1, ah2, ah3, bl.z, bl.w);
    }

    // ---- epilogue: bias + store ----
    const size_t pixbase = (((size_t)((b << 7) + h)) << 7) + w0;
    #pragma unroll
    for (int nt = 0; nt < 2; nt++) {
        int col = n0 + (nt << 3) + (tg << 1);
        float2 bb = *(const float2*)(b2 + col);
        *(float2*)(y + ((pixbase + m0 + g) << 6) + col) =
            make_float2(o[nt][0] + bb.x, o[nt][1] + bb.y);
        *(float2*)(y + ((pixbase + m0 + g + 8) << 6) + col) =
            make_float2(o[nt][2] + bb.x, o[nt][3] + bb.y);
    }
}

// ---------------------------------------------------------------------------
extern "C" void kernel_launch(void* const* d_in, const int* in_sizes, int n_in,
                              void* d_out, int out_size)
{
    const float* x   = (const float*)d_in[0];
    const float* c   = (const float*)d_in[1];
    const float* Wv  = (const float*)d_in[6];
    const float* bv  = (const float*)d_in[7];
    const float* Wo  = (const float*)d_in[8];
    const float* bo  = (const float*)d_in[9];
    const float* lng = (const float*)d_in[10];
    const float* lnb = (const float*)d_in[11];
    const float* pk  = (const float*)d_in[12];
    const float* W1  = (const float*)d_in[13];
    const float* b1  = (const float*)d_in[14];
    const float* W2  = (const float*)d_in[15];
    const float* b2  = (const float*)d_in[16];

    float* y     = (float*)d_out;
    float* outc2 = y + (size_t)8 * 128 * 128 * 64;

    prep_ctx_kernel<<<81, THREADS>>>(W1, W2, c, Wv, bv, Wo, bo, lng, lnb, outc2);

    cudaFuncSetAttribute(nca_kernel, cudaFuncAttributeMaxDynamicSharedMemorySize, SMEM_BYTES);
    nca_kernel<<<4096, THREADS, SMEM_BYTES>>>(x, pk, b1, b2, y);
}